// round 17
// baseline (speedup 1.0000x reference)
#include <cuda_runtime.h>
#include <math.h>

#define CCH 62
#define TT  2000
#define NB  256
#define TIL 128
#define NTILE ((TT + TIL - 1) / TIL)   // 16

typedef unsigned long long ull;

// ---- packed f32x2 helpers (sm_103a FFMA2 pipe; ptxas never auto-fuses) ----
__device__ __forceinline__ ull pk(float lo, float hi) {
    ull r; asm("mov.b64 %0, {%1, %2};" : "=l"(r) : "f"(lo), "f"(hi)); return r;
}
__device__ __forceinline__ float2 upk(ull v) {
    float2 r; asm("mov.b64 {%0, %1}, %2;" : "=f"(r.x), "=f"(r.y) : "l"(v)); return r;
}
__device__ __forceinline__ ull fma2(ull a, ull b, ull c) {
    ull d; asm("fma.rn.f32x2 %0, %1, %2, %3;" : "=l"(d) : "l"(a), "l"(b), "l"(c)); return d;
}
__device__ __forceinline__ ull mul2(ull a, ull b) {
    ull d; asm("mul.rn.f32x2 %0, %1, %2;" : "=l"(d) : "l"(a), "l"(b)); return d;
}

// ---------------------------------------------------------------------------
// Fused kernel (R16 structure + f32x2 packed arithmetic):
// covariance (smem) -> A = W Cov W^T + eps I -> two-sided parallel Jacobi
// (ping-pong A, 1 barrier/round) -> log-map GEMM -> triu -> MLP -> head.
// ---------------------------------------------------------------------------
__global__ __launch_bounds__(256, 2) void fused_kernel(
    const float* __restrict__ x,
    const float* __restrict__ conv_w,
    const float* __restrict__ proj_w, const float* __restrict__ proj_b,
    const float* __restrict__ head_w, const float* __restrict__ head_b,
    float* __restrict__ out)
{
    __shared__ __align__(16) float S[16324];
    float* Abuf0 = S;
    float* Abuf1 = S + 4160;
    float* Vsm   = S + 8320;
    float* Wbuf  = S + 12416;
    float* ssum  = S + 16260;
    float* xs    = S;                 // cov-phase alias of Abuf0+Abuf1

    float* vec  = Wbuf;               // [1953] (Wbuf dead when live)
    float* logl = Wbuf + 2048;        // [64]
    float* feat = Wbuf + 2112;        // [64]

    const int b    = blockIdx.x;
    const int tid  = threadIdx.x;
    const int wid  = tid >> 5;
    const int lane = tid & 31;
    const int ti   = tid >> 4;
    const int tj   = tid & 15;

    // ================= cov phase =================
    int bi = 0, bj = 0;
    const bool act = (tid < 136);
    if (act) {
        int z = tid;
        while (z >= 16 - bi) { z -= 16 - bi; bi++; }
        bj = bi + z;
    }

    {
        ull accP[16];
#pragma unroll
        for (int r = 0; r < 16; r++) accP[r] = 0ull;
        float mysum = 0.f;

        const float* xb = x + (size_t)b * CCH * TT;

        for (int tile = 0; tile < NTILE; tile++) {
            const int t0 = tile * TIL;
#pragma unroll
            for (int k = 0; k < 16; k++) {
                const int f = tid + (k << 8);
                const int c = f >> 6;
                const int u = f & 63;
                const int t = t0 + u * 2;
                float2 v = make_float2(0.f, 0.f);
                if (c < CCH && t < TT) v = *(const float2*)(xb + c * TT + t);
                *(float2*)(xs + c * 130 + u * 2) = v;
            }
            __syncthreads();

            if (tid < CCH) {
                const float2* rp = (const float2*)(xs + tid * 130);
#pragma unroll 8
                for (int tl = 0; tl < 64; tl++) {
                    const float2 v = rp[tl];
                    mysum += v.x + v.y;
                }
            }

            if (act) {
                const ull* r0 = (const ull*)(xs + (4 * bi + 0) * 130);
                const ull* r1 = (const ull*)(xs + (4 * bi + 1) * 130);
                const ull* r2 = (const ull*)(xs + (4 * bi + 2) * 130);
                const ull* r3 = (const ull*)(xs + (4 * bi + 3) * 130);
                const ull* c0 = (const ull*)(xs + (4 * bj + 0) * 130);
                const ull* c1 = (const ull*)(xs + (4 * bj + 1) * 130);
                const ull* c2 = (const ull*)(xs + (4 * bj + 2) * 130);
                const ull* c3 = (const ull*)(xs + (4 * bj + 3) * 130);

#pragma unroll 4
                for (int tl = 0; tl < 64; tl++) {
                    const ull a0 = r0[tl], a1 = r1[tl], a2 = r2[tl], a3 = r3[tl];
                    const ull b0 = c0[tl], b1 = c1[tl], b2 = c2[tl], b3 = c3[tl];
                    accP[0]  = fma2(a0, b0, accP[0]);
                    accP[1]  = fma2(a0, b1, accP[1]);
                    accP[2]  = fma2(a0, b2, accP[2]);
                    accP[3]  = fma2(a0, b3, accP[3]);
                    accP[4]  = fma2(a1, b0, accP[4]);
                    accP[5]  = fma2(a1, b1, accP[5]);
                    accP[6]  = fma2(a1, b2, accP[6]);
                    accP[7]  = fma2(a1, b3, accP[7]);
                    accP[8]  = fma2(a2, b0, accP[8]);
                    accP[9]  = fma2(a2, b1, accP[9]);
                    accP[10] = fma2(a2, b2, accP[10]);
                    accP[11] = fma2(a2, b3, accP[11]);
                    accP[12] = fma2(a3, b0, accP[12]);
                    accP[13] = fma2(a3, b1, accP[13]);
                    accP[14] = fma2(a3, b2, accP[14]);
                    accP[15] = fma2(a3, b3, accP[15]);
                }
            }
            __syncthreads();
        }

        if (tid < 64) ssum[tid] = (tid < CCH) ? mysum : 0.f;
        __syncthreads();          // xs dead from here; Abuf0 writes safe

        if (act) {
#pragma unroll
            for (int r = 0; r < 4; r++) {
#pragma unroll
                for (int u = 0; u < 4; u++) {
                    const int i = 4 * bi + r;
                    const int j = 4 * bj + u;
                    const float2 s2 = upk(accP[r * 4 + u]);
                    const float v = ((s2.x + s2.y) -
                                     ssum[i] * ssum[j] * (1.f / 2000.f)) * (1.f / 1999.f);
                    Abuf0[i * 65 + j] = v;
                    Abuf0[j * 65 + i] = v;
                }
            }
        }
    }
    for (int idx = tid; idx < 62 * 62; idx += 256) Wbuf[idx] = conv_w[idx];
    __syncthreads();

    // ================= conjugation: A = W Cov W^T =================
    {
        float acc[16];
#pragma unroll
        for (int r = 0; r < 16; r++) acc[r] = 0.f;
        for (int k = 0; k < 62; k++) {
            float wv[4], cv[4];
#pragma unroll
            for (int r = 0; r < 4; r++) {
                const int i = 4 * ti + r;
                wv[r] = (i < 62) ? Wbuf[i * 62 + k] : 0.f;
            }
#pragma unroll
            for (int u = 0; u < 4; u++) cv[u] = Abuf0[k * 65 + 4 * tj + u];
#pragma unroll
            for (int r = 0; r < 4; r++)
#pragma unroll
                for (int u = 0; u < 4; u++) acc[r * 4 + u] += wv[r] * cv[u];
        }
#pragma unroll
        for (int r = 0; r < 4; r++)
#pragma unroll
            for (int u = 0; u < 4; u++)
                Vsm[(4 * ti + r) * 64 + 4 * tj + u] = acc[r * 4 + u];
    }
    __syncthreads();

    {
        float acc[16];
#pragma unroll
        for (int r = 0; r < 16; r++) acc[r] = 0.f;
        for (int k = 0; k < 62; k++) {
            float mv[4], wv[4];
#pragma unroll
            for (int r = 0; r < 4; r++) mv[r] = Vsm[(4 * ti + r) * 64 + k];
#pragma unroll
            for (int u = 0; u < 4; u++) {
                const int j = 4 * tj + u;
                wv[u] = (j < 62) ? Wbuf[j * 62 + k] : 0.f;
            }
#pragma unroll
            for (int r = 0; r < 4; r++)
#pragma unroll
                for (int u = 0; u < 4; u++) acc[r * 4 + u] += mv[r] * wv[u];
        }
#pragma unroll
        for (int r = 0; r < 4; r++)
#pragma unroll
            for (int u = 0; u < 4; u++)
                Abuf0[(4 * ti + r) * 65 + 4 * tj + u] = acc[r * 4 + u];
    }
    __syncthreads();

    // ---- symmetrize + SPD eps + pad diag ----
    {
        float v[16];
#pragma unroll
        for (int r = 0; r < 4; r++)
#pragma unroll
            for (int u = 0; u < 4; u++) {
                const int i = 4 * ti + r, j = 4 * tj + u;
                v[r * 4 + u] = 0.5f * (Abuf0[i * 65 + j] + Abuf0[j * 65 + i]);
            }
        __syncthreads();
#pragma unroll
        for (int r = 0; r < 4; r++)
#pragma unroll
            for (int u = 0; u < 4; u++) {
                const int i = 4 * ti + r, j = 4 * tj + u;
                float val = v[r * 4 + u];
                if (i == j) val = (i < 62) ? val + 1e-3f : 1.0f;
                Abuf0[i * 65 + j] = val;
            }
    }
    for (int idx = tid; idx < 4096; idx += 256)
        Vsm[idx] = ((idx >> 6) == (idx & 63)) ? 1.f : 0.f;
    __syncthreads();

    // ================= two-sided parallel Jacobi =================
    int pReg = (lane == 0) ? 63 : lane;
    int qReg = (lane == 0) ? 0  : 63 - lane;
    int prowR[4], qrowR[4];
#pragma unroll
    for (int it = 0; it < 4; it++) {
        const int kk = 8 * it + wid;
        prowR[it] = (kk == 0) ? 63 : kk;
        qrowR[it] = (kk == 0) ? 0  : 63 - kk;
    }
    const bool kk0 = (wid == 0);

    float* Acur = Abuf0;
    float* Anxt = Abuf1;
    for (int sweep = 0; sweep < 9; sweep++) {
        bool any_sweep_rot = false;
        for (int r = 0; r < 63; r++) {
            const int p = pReg, q = qReg;
            int prow[4], qrow[4];
#pragma unroll
            for (int it = 0; it < 4; it++) { prow[it] = prowR[it]; qrow[it] = qrowR[it]; }

            // advance tournament registers (even on skipped rounds)
            if (lane) { pReg++; if (pReg == 63) pReg = 0; }
            qReg++; if (qReg == 63) qReg = 0;
#pragma unroll
            for (int it = 0; it < 4; it++) {
                if (!(it == 0 && kk0)) { prowR[it]++; if (prowR[it] == 63) prowR[it] = 0; }
                qrowR[it]++; if (qrowR[it] == 63) qrowR[it] = 0;
            }

            const float app = Acur[p * 65 + p];
            const float aqq = Acur[q * 65 + q];
            const float apq = Acur[p * 65 + q];
            float cO = 1.f, sO = 0.f;
            if (apq * apq > 3e-8f * app * aqq) {    // relative skip
                const float tau = (aqq - app) / (2.f * apq);
                const float t2  = ((tau >= 0.f) ? 1.f : -1.f) /
                                  (fabsf(tau) + sqrtf(1.f + tau * tau));
                cO = rsqrtf(1.f + t2 * t2);
                sO = t2 * cO;
            }
            const unsigned rotmask = __ballot_sync(0xffffffffu, sO != 0.f);
            if (rotmask == 0u) continue;   // skipped round: no writes, no flip
            any_sweep_rot = true;

            // loads: addresses ready at round entry -> batch immediately
            float a00[4], a01[4], a10[4], a11[4];
            ull xpU[4], xqU[4];
#pragma unroll
            for (int it = 0; it < 4; it++) {
                const int rp = prow[it] * 65, rq = qrow[it] * 65;
                a00[it] = Acur[rp + p]; a01[it] = Acur[rp + q];
                a10[it] = Acur[rq + p]; a11[it] = Acur[rq + q];
            }
#pragma unroll
            for (int it = 0; it < 4; it++) {
                xpU[it] = *((const ull*)(Vsm + (prow[it] << 6)) + lane);
                xqU[it] = *((const ull*)(Vsm + (qrow[it] << 6)) + lane);
            }
            float cr[4], sr[4];
#pragma unroll
            for (int it = 0; it < 4; it++) {
                const int kk = 8 * it + wid;                       // warp-uniform
                cr[it] = __shfl_sync(0xffffffffu, cO, kk);
                sr[it] = __shfl_sync(0xffffffffu, sO, kk);
            }

            const ull cOP  = pk(cO, cO);
            const ull sOP  = pk(sO, sO);
            const ull nsOP = pk(-sO, -sO);

            // A update packed across it pairs (both rotations elementwise)
#pragma unroll
            for (int h = 0; h < 2; h++) {
                const int i0 = 2 * h, i1 = 2 * h + 1;
                const ull crP  = pk(cr[i0], cr[i1]);
                const ull srP  = pk(sr[i0], sr[i1]);
                const ull nsrP = pk(-sr[i0], -sr[i1]);
                const ull A00 = pk(a00[i0], a00[i1]);
                const ull A01 = pk(a01[i0], a01[i1]);
                const ull A10 = pk(a10[i0], a10[i1]);
                const ull A11 = pk(a11[i0], a11[i1]);
                const ull B00 = fma2(crP, A00, mul2(nsrP, A10));
                const ull B01 = fma2(crP, A01, mul2(nsrP, A11));
                const ull B10 = fma2(srP, A00, mul2(crP, A10));
                const ull B11 = fma2(srP, A01, mul2(crP, A11));
                const ull OPP = fma2(cOP, B00, mul2(nsOP, B01));
                const ull OPQ = fma2(sOP, B00, mul2(cOP, B01));
                const ull OQP = fma2(cOP, B10, mul2(nsOP, B11));
                const ull OQQ = fma2(sOP, B10, mul2(cOP, B11));
                float2 v;
                v = upk(OPP); Anxt[prow[i0] * 65 + p] = v.x; Anxt[prow[i1] * 65 + p] = v.y;
                v = upk(OPQ); Anxt[prow[i0] * 65 + q] = v.x; Anxt[prow[i1] * 65 + q] = v.y;
                v = upk(OQP); Anxt[qrow[i0] * 65 + p] = v.x; Anxt[qrow[i1] * 65 + p] = v.y;
                v = upk(OQQ); Anxt[qrow[i0] * 65 + q] = v.x; Anxt[qrow[i1] * 65 + q] = v.y;
            }

            // V update packed (loads/stores already 64-bit)
#pragma unroll
            for (int it = 0; it < 4; it++) {
                const ull crV  = pk(cr[it], cr[it]);
                const ull srV  = pk(sr[it], sr[it]);
                const ull nsrV = pk(-sr[it], -sr[it]);
                const ull np = fma2(crV, xpU[it], mul2(nsrV, xqU[it]));
                const ull nq = fma2(srV, xpU[it], mul2(crV, xqU[it]));
                *((ull*)(Vsm + (prow[it] << 6)) + lane) = np;
                *((ull*)(Vsm + (qrow[it] << 6)) + lane) = nq;
            }
            // flip; single barrier orders writes vs next round's reads
            float* t = Acur; Acur = Anxt; Anxt = t;
            __syncthreads();
        }

        if (!any_sweep_rot) break;
    }

    // ================= log-map + epilogue =================
    if (tid < 64) {
        const float d = Acur[tid * 65 + tid];
        logl[tid] = logf(fmaxf(d, 1e-6f));
    }
    __syncthreads();
    for (int idx = tid; idx < 4096; idx += 256) {
        const int k = idx >> 6, i = idx & 63;
        Acur[k * 65 + i] = logl[k] * Vsm[idx];
    }
    __syncthreads();

    // log_cov = B^T Q via 4x4 block GEMM (packed), triu straight to vec
    {
        ull accP[8];
#pragma unroll
        for (int r = 0; r < 8; r++) accP[r] = 0ull;
        for (int k = 0; k < 64; k++) {
            float bb[4];
#pragma unroll
            for (int r = 0; r < 4; r++) bb[r] = Acur[k * 65 + 4 * ti + r];
            const float4 qv = *((const float4*)(Vsm + k * 64) + tj);
            const ull qlo = pk(qv.x, qv.y);
            const ull qhi = pk(qv.z, qv.w);
#pragma unroll
            for (int r = 0; r < 4; r++) {
                const ull bbP = pk(bb[r], bb[r]);
                accP[2 * r]     = fma2(bbP, qlo, accP[2 * r]);
                accP[2 * r + 1] = fma2(bbP, qhi, accP[2 * r + 1]);
            }
        }
        __syncthreads();   // Acur/Vsm reads done before vec (Wbuf) written
#pragma unroll
        for (int r = 0; r < 4; r++) {
            const float2 v0 = upk(accP[2 * r]);
            const float2 v1 = upk(accP[2 * r + 1]);
            const float av[4] = { v0.x, v0.y, v1.x, v1.y };
#pragma unroll
            for (int u = 0; u < 4; u++) {
                const int i = 4 * ti + r, j = 4 * tj + u;
                if (i <= j && j < 62)
                    vec[i * (125 - i) / 2 + (j - i)] = av[u];
            }
        }
    }
    __syncthreads();

    // MLP: feat = relu(vec @ proj^T + b), 8 outputs per warp
    {
#pragma unroll
        for (int hh = 0; hh < 8; hh++) {
            const int h = (wid << 3) + hh;
            const float* pw = proj_w + h * 1953;
            float acc = 0.f;
            for (int i = lane; i < 1953; i += 32) acc += vec[i] * pw[i];
#pragma unroll
            for (int off = 16; off; off >>= 1)
                acc += __shfl_down_sync(0xffffffffu, acc, off);
            if (lane == 0) feat[h] = fmaxf(acc + proj_b[h], 0.f);
        }
    }
    __syncthreads();

    // head: 3 logits
    if (tid < 3) {
        float acc = head_b[tid];
        const float* hw = head_w + tid * 64;
#pragma unroll
        for (int h = 0; h < 64; h++) acc += feat[h] * hw[h];
        out[b * 3 + tid] = acc;
    }
}

// ---------------------------------------------------------------------------
extern "C" void kernel_launch(void* const* d_in, const int* in_sizes, int n_in,
                              void* d_out, int out_size)
{
    const float* x      = (const float*)d_in[0];
    const float* conv_w = (const float*)d_in[1];
    // d_in[2] = conv_b: cancels exactly under mean-centering; unused.
    const float* proj_w = (const float*)d_in[3];
    const float* proj_b = (const float*)d_in[4];
    const float* head_w = (const float*)d_in[5];
    const float* head_b = (const float*)d_in[6];

    int B = in_sizes[0] / (CCH * TT);
    if (B > NB) B = NB;

    fused_kernel<<<B, 256>>>(x, conv_w, proj_w, proj_b, head_w, head_b,
                             (float*)d_out);
}